// round 5
// baseline (speedup 1.0000x reference)
#include <cuda_runtime.h>
#include <cuda_bf16.h>
#include <cstdint>
#include <math.h>

#define EPSV 1e-5f
constexpr int B     = 8;
constexpr int C     = 512;
constexpr int NH    = 8;
constexpr int KD    = 32;
constexpr int HD    = 64;
constexpr int HQKV  = 1024;
constexpr int NPIX  = 1600;
constexpr int IH    = 40;
constexpr int IW    = 40;
constexpr int K3    = 1536;       // 3 * 512
constexpr float SCALE = 0.17677669529663687f;

__device__ __align__(16) float g_qkv[(size_t)B * HQKV * NPIX];
__device__ __align__(16) float g_att[(size_t)B * C * NPIX];
__device__ __align__(16) float g_y  [(size_t)B * C * NPIX];
__device__ __align__(16) __nv_bfloat16 g_wcq[(size_t)HQKV * K3];     // qkv W triple
__device__ __align__(16) __nv_bfloat16 g_wcp[(size_t)C * K3];        // proj W triple
__device__ __align__(16) __nv_bfloat16 g_xc [(size_t)B * NPIX * K3]; // x / y transposed triple

// ===================== helpers =====================
__device__ __forceinline__ float bf_round(float x) {
    return __bfloat162float(__float2bfloat16_rn(x));
}
__device__ __forceinline__ uint32_t pack2(float hi, float lo) {
    uint32_t r;
    asm("cvt.rn.bf16x2.f32 %0, %1, %2;" : "=r"(r) : "f"(hi), "f"(lo));
    return r;
}
__device__ __forceinline__ void mma16816(float* c, const uint32_t* a, uint32_t b0, uint32_t b1) {
    asm volatile(
        "mma.sync.aligned.m16n8k16.row.col.f32.bf16.bf16.f32 "
        "{%0,%1,%2,%3}, {%4,%5,%6,%7}, {%8,%9}, {%0,%1,%2,%3};"
        : "+f"(c[0]), "+f"(c[1]), "+f"(c[2]), "+f"(c[3])
        : "r"(a[0]), "r"(a[1]), "r"(a[2]), "r"(a[3]), "r"(b0), "r"(b1));
}
__device__ __forceinline__ void cp16(uint32_t dst, const void* src) {
    asm volatile("cp.async.cg.shared.global [%0], [%1], 16;" :: "r"(dst), "l"(src));
}
#define CP_COMMIT() asm volatile("cp.async.commit_group;" ::: "memory")
#define CP_WAIT(n)  asm volatile("cp.async.wait_group %0;" :: "n"(n) : "memory")

// ================= prep: W -> triple bf16 [m][3k]: (h,h,l) ==================
__global__ __launch_bounds__(256) void prep_w(const float* __restrict__ W,
                                              __nv_bfloat16* __restrict__ out, int MK)
{
    int i = blockIdx.x * 256 + threadIdx.x;
    if (i >= MK) return;
    int m = i >> 9, k = i & 511;            // K = 512
    float v = W[i];
    float h = bf_round(v);
    __nv_bfloat16* d = out + (size_t)m * K3 + 3 * k;
    d[0] = __float2bfloat16_rn(h);
    d[1] = __float2bfloat16_rn(h);
    d[2] = __float2bfloat16_rn(v - h);
}

// ====== prep: X [b][k][n] -> triple-transposed bf16 [b][n][3k]: (h,l,h) =====
__global__ __launch_bounds__(256) void prep_xt(const float* __restrict__ X,
                                               __nv_bfloat16* __restrict__ out)
{
    __shared__ float t[32][33];
    const int tid = threadIdx.x;
    const int k0 = blockIdx.x * 32, n0 = blockIdx.y * 32, b = blockIdx.z;
    const float* Xb = X + (size_t)b * 512 * NPIX;
    int tr = tid >> 5, tc = tid & 31;
    #pragma unroll
    for (int p = 0; p < 4; p++)
        t[tr + p * 8][tc] = Xb[(size_t)(k0 + tr + p * 8) * NPIX + n0 + tc];
    __syncthreads();
    int nr = tid >> 3, kq = (tid & 7) * 4;
    __nv_bfloat16* dst = out + (size_t)b * NPIX * K3 + (size_t)(n0 + nr) * K3 + (k0 + kq) * 3;
    #pragma unroll
    for (int q = 0; q < 4; q++) {
        float v = t[kq + q][nr];
        float h = bf_round(v);
        dst[q * 3 + 0] = __float2bfloat16_rn(h);
        dst[q * 3 + 1] = __float2bfloat16_rn(v - h);
        dst[q * 3 + 2] = __float2bfloat16_rn(h);
    }
}

// ============== pipelined bf16 GEMM (K'=1536) + fused BN ====================
// out[b][m][n] = BN( sum_k' wc[m][k'] * xc[b][n][k'] )
// CTA 128m x 128n, 8 warps (4M x 2N), warp 32x64, K-chunk 32, cp.async 2-stage.
constexpr int KC  = 32;
constexpr int NIT = K3 / KC;   // 48

__global__ __launch_bounds__(256, 2) void gemm3_bn(
    const __nv_bfloat16* __restrict__ wc, const __nv_bfloat16* __restrict__ xc,
    const float* __restrict__ gamma, const float* __restrict__ beta,
    const float* __restrict__ mean,  const float* __restrict__ var,
    float* __restrict__ out, int M)
{
    __shared__ __align__(16) __nv_bfloat16 sw[2][128 * 40];
    __shared__ __align__(16) __nv_bfloat16 sx[2][128 * 40];
    __shared__ float sbn[128][2];

    const int tid  = threadIdx.x;
    const int wid  = tid >> 5;
    const int lane = tid & 31;
    const int g    = lane >> 2;
    const int tig  = lane & 3;
    const int wm   = wid >> 1;
    const int wn   = wid & 1;
    const int n0   = blockIdx.x * 128;
    const int m0   = blockIdx.y * 128;
    const int b    = blockIdx.z;
    const __nv_bfloat16* xb = xc + (size_t)b * NPIX * K3;

    if (tid < 128) {
        int m = m0 + tid;
        float inv = gamma[m] * rsqrtf(var[m] + EPSV);
        sbn[tid][0] = inv;
        sbn[tid][1] = beta[m] - mean[m] * inv;
    }

    // per-thread cp.async assignment: chunks tid, tid+256 (row = c>>2, seg = c&3)
    const int rowA = tid >> 2,        segA = tid & 3;
    const int rowB = (tid + 256) >> 2, segB = (tid + 256) & 3;
    int nA = n0 + rowA; if (nA > NPIX - 1) nA = NPIX - 1;
    int nB = n0 + rowB; if (nB > NPIX - 1) nB = NPIX - 1;
    const uint32_t swb = (uint32_t)__cvta_generic_to_shared(&sw[0][0]);
    const uint32_t sxb = (uint32_t)__cvta_generic_to_shared(&sx[0][0]);
    const uint32_t dWA = rowA * 80 + segA * 16, dWB = rowB * 80 + segB * 16;

    float acc[2][8][4];
    #pragma unroll
    for (int i = 0; i < 2; i++)
        #pragma unroll
        for (int j = 0; j < 8; j++)
            #pragma unroll
            for (int l = 0; l < 4; l++) acc[i][j][l] = 0.f;

    auto issue = [&](int buf, int k0) {
        uint32_t bo = buf * (128 * 40 * 2);
        cp16(swb + bo + dWA, wc + (size_t)(m0 + rowA) * K3 + k0 + segA * 8);
        cp16(swb + bo + dWB, wc + (size_t)(m0 + rowB) * K3 + k0 + segB * 8);
        cp16(sxb + bo + dWA, xb + (size_t)nA * K3 + k0 + segA * 8);
        cp16(sxb + bo + dWB, xb + (size_t)nB * K3 + k0 + segB * 8);
    };

    issue(0, 0); CP_COMMIT();
    int buf = 0;
    #pragma unroll 1
    for (int it = 0; it < NIT; it++) {
        if (it + 1 < NIT) { issue(buf ^ 1, (it + 1) * KC); CP_COMMIT(); CP_WAIT(1); }
        else              { CP_WAIT(0); }
        __syncthreads();

        const __nv_bfloat16* w_s = sw[buf];
        const __nv_bfloat16* x_s = sx[buf];
        #pragma unroll
        for (int ks = 0; ks < 2; ks++) {
            const int cb = ks * 16 + 2 * tig;
            uint32_t aW[2][4];
            #pragma unroll
            for (int mf = 0; mf < 2; mf++) {
                int r0 = wm * 32 + mf * 16 + g;
                aW[mf][0] = *(const uint32_t*)&w_s[r0 * 40 + cb];
                aW[mf][1] = *(const uint32_t*)&w_s[(r0 + 8) * 40 + cb];
                aW[mf][2] = *(const uint32_t*)&w_s[r0 * 40 + cb + 8];
                aW[mf][3] = *(const uint32_t*)&w_s[(r0 + 8) * 40 + cb + 8];
            }
            #pragma unroll
            for (int nf = 0; nf < 8; nf++) {
                int nr = wn * 64 + nf * 8 + g;
                uint32_t b0 = *(const uint32_t*)&x_s[nr * 40 + cb];
                uint32_t b1 = *(const uint32_t*)&x_s[nr * 40 + cb + 8];
                mma16816(acc[0][nf], aW[0], b0, b1);
                mma16816(acc[1][nf], aW[1], b0, b1);
            }
        }
        __syncthreads();
        buf ^= 1;
    }

    // ---- epilogue: BN + store ----
    #pragma unroll
    for (int mf = 0; mf < 2; mf++) {
        int mla = wm * 32 + mf * 16 + g;
        int mlb = mla + 8;
        float inva = sbn[mla][0], adda = sbn[mla][1];
        float invb = sbn[mlb][0], addb = sbn[mlb][1];
        float* rowa = out + ((size_t)b * M + m0 + mla) * NPIX;
        float* rowb = out + ((size_t)b * M + m0 + mlb) * NPIX;
        #pragma unroll
        for (int nf = 0; nf < 8; nf++) {
            int n = n0 + wn * 64 + nf * 8 + 2 * tig;
            if (n < NPIX) {
                *(float2*)&rowa[n] = make_float2(acc[0][nf][0] * inva + adda,
                                                 acc[0][nf][1] * inva + adda);
                *(float2*)&rowb[n] = make_float2(acc[0][nf][2] * invb + addb,
                                                 acc[0][nf][3] * invb + addb);
            }
        }
        // second m-fragment (mf index 1 of acc)
        (void)0;
    }
    // NOTE: loop above only stored acc[0]; store acc[1] here identically.
    #pragma unroll
    for (int nf = 0; nf < 8; nf++) {
        int mla = wm * 32 + 16 + g;     // mf=1
        int mlb = mla + 8;
        float inva = sbn[mla][0], adda = sbn[mla][1];
        float invb = sbn[mlb][0], addb = sbn[mlb][1];
        float* rowa = out + ((size_t)b * M + m0 + mla) * NPIX;
        float* rowb = out + ((size_t)b * M + m0 + mlb) * NPIX;
        int n = n0 + wn * 64 + nf * 8 + 2 * tig;
        if (n < NPIX) {
            *(float2*)&rowa[n] = make_float2(acc[1][nf][0] * inva + adda,
                                             acc[1][nf][1] * inva + adda);
            *(float2*)&rowb[n] = make_float2(acc[1][nf][2] * invb + addb,
                                             acc[1][nf][3] * invb + addb);
        }
    }
}

// ============ FlashAttention-2 style HMMA attention (unchanged) =============
constexpr int SQH = 0, SQL = 9216, SKH = 18432, SKL = 23040, SVH = 27648, SVL = 36864;

__global__ __launch_bounds__(256) void attn_hmma_kernel()
{
    __shared__ __align__(16) char sm[46080];
    __nv_bfloat16* qh = (__nv_bfloat16*)(sm + SQH);
    __nv_bfloat16* ql = (__nv_bfloat16*)(sm + SQL);
    __nv_bfloat16* kh = (__nv_bfloat16*)(sm + SKH);
    __nv_bfloat16* kl = (__nv_bfloat16*)(sm + SKL);
    __nv_bfloat16* vh = (__nv_bfloat16*)(sm + SVH);
    __nv_bfloat16* vl = (__nv_bfloat16*)(sm + SVL);
    float* sO = (float*)sm;

    const int tid  = threadIdx.x;
    const int wid  = tid >> 5;
    const int lane = tid & 31;
    const int g    = lane >> 2;
    const int tig  = lane & 3;
    const int bh   = blockIdx.y;
    const int n0   = blockIdx.x * 128;

    const float* qp = g_qkv + (size_t)bh * 128 * NPIX;
    const float* kp = qp + (size_t)KD * NPIX;
    const float* vp = qp + (size_t)2 * KD * NPIX;

    for (int idx = tid; idx < 128 * 32; idx += 256) {
        int c = idx >> 7, q = idx & 127;
        int n = n0 + q; if (n > NPIX - 1) n = NPIX - 1;
        float v = qp[(size_t)c * NPIX + n] * SCALE;
        float h = bf_round(v);
        qh[q * 36 + c] = __float2bfloat16_rn(h);
        ql[q * 36 + c] = __float2bfloat16_rn(v - h);
    }
    __syncthreads();

    uint32_t aQh[2][4], aQl[2][4];
    {
        int r0 = wid * 16 + g;
        #pragma unroll
        for (int ks = 0; ks < 2; ks++) {
            int cb = ks * 16 + 2 * tig;
            aQh[ks][0] = *(const uint32_t*)&qh[r0 * 36 + cb];
            aQh[ks][1] = *(const uint32_t*)&qh[(r0 + 8) * 36 + cb];
            aQh[ks][2] = *(const uint32_t*)&qh[r0 * 36 + cb + 8];
            aQh[ks][3] = *(const uint32_t*)&qh[(r0 + 8) * 36 + cb + 8];
            aQl[ks][0] = *(const uint32_t*)&ql[r0 * 36 + cb];
            aQl[ks][1] = *(const uint32_t*)&ql[(r0 + 8) * 36 + cb];
            aQl[ks][2] = *(const uint32_t*)&ql[r0 * 36 + cb + 8];
            aQl[ks][3] = *(const uint32_t*)&ql[(r0 + 8) * 36 + cb + 8];
        }
    }

    float o[8][4];
    #pragma unroll
    for (int i = 0; i < 8; i++)
        #pragma unroll
        for (int j = 0; j < 4; j++) o[i][j] = 0.f;
    float rsum0 = 0.f, rsum1 = 0.f;

    for (int t = 0; t < 25; t++) {
        const int m0 = t * 64;
        __syncthreads();
        for (int idx = tid; idx < 64 * 32; idx += 256) {
            int c = idx >> 6, k = idx & 63;
            float v = kp[(size_t)c * NPIX + m0 + k];
            float h = bf_round(v);
            kh[k * 36 + c] = __float2bfloat16_rn(h);
            kl[k * 36 + c] = __float2bfloat16_rn(v - h);
        }
        for (int idx = tid; idx < 64 * 64; idx += 256) {
            int d = idx >> 6, k = idx & 63;
            float v = vp[(size_t)d * NPIX + m0 + k];
            float h = bf_round(v);
            vh[d * 72 + k] = __float2bfloat16_rn(h);
            vl[d * 72 + k] = __float2bfloat16_rn(v - h);
        }
        __syncthreads();

        float s[8][4];
        #pragma unroll
        for (int nt = 0; nt < 8; nt++) {
            s[nt][0] = s[nt][1] = s[nt][2] = s[nt][3] = 0.f;
            #pragma unroll
            for (int ks = 0; ks < 2; ks++) {
                int key = nt * 8 + g;
                int cb  = ks * 16 + 2 * tig;
                uint32_t bh0 = *(const uint32_t*)&kh[key * 36 + cb];
                uint32_t bh1 = *(const uint32_t*)&kh[key * 36 + cb + 8];
                uint32_t bl0 = *(const uint32_t*)&kl[key * 36 + cb];
                uint32_t bl1 = *(const uint32_t*)&kl[key * 36 + cb + 8];
                mma16816(s[nt], aQh[ks], bh0, bh1);
                mma16816(s[nt], aQh[ks], bl0, bl1);
                mma16816(s[nt], aQl[ks], bh0, bh1);
            }
        }

        #pragma unroll
        for (int nt = 0; nt < 8; nt++) {
            s[nt][0] = __expf(s[nt][0]);
            s[nt][1] = __expf(s[nt][1]);
            s[nt][2] = __expf(s[nt][2]);
            s[nt][3] = __expf(s[nt][3]);
            rsum0 += s[nt][0] + s[nt][1];
            rsum1 += s[nt][2] + s[nt][3];
        }

        #pragma unroll
        for (int ks = 0; ks < 4; ks++) {
            const int ta = 2 * ks, tb_ = 2 * ks + 1;
            uint32_t ah[4], al[4];
            {
                float p0 = s[ta][0],  p1 = s[ta][1];
                float h0 = bf_round(p0), h1 = bf_round(p1);
                ah[0] = pack2(h1, h0); al[0] = pack2(p1 - h1, p0 - h0);
                p0 = s[ta][2]; p1 = s[ta][3];
                h0 = bf_round(p0); h1 = bf_round(p1);
                ah[1] = pack2(h1, h0); al[1] = pack2(p1 - h1, p0 - h0);
                p0 = s[tb_][0]; p1 = s[tb_][1];
                h0 = bf_round(p0); h1 = bf_round(p1);
                ah[2] = pack2(h1, h0); al[2] = pack2(p1 - h1, p0 - h0);
                p0 = s[tb_][2]; p1 = s[tb_][3];
                h0 = bf_round(p0); h1 = bf_round(p1);
                ah[3] = pack2(h1, h0); al[3] = pack2(p1 - h1, p0 - h0);
            }
            #pragma unroll
            for (int nt = 0; nt < 8; nt++) {
                int d  = nt * 8 + g;
                int kb = ks * 16 + 2 * tig;
                uint32_t bh0 = *(const uint32_t*)&vh[d * 72 + kb];
                uint32_t bh1 = *(const uint32_t*)&vh[d * 72 + kb + 8];
                uint32_t bl0 = *(const uint32_t*)&vl[d * 72 + kb];
                uint32_t bl1 = *(const uint32_t*)&vl[d * 72 + kb + 8];
                mma16816(o[nt], ah, bh0, bh1);
                mma16816(o[nt], ah, bl0, bl1);
                mma16816(o[nt], al, bh0, bh1);
            }
        }
    }

    rsum0 += __shfl_xor_sync(0xffffffffu, rsum0, 1);
    rsum0 += __shfl_xor_sync(0xffffffffu, rsum0, 2);
    rsum1 += __shfl_xor_sync(0xffffffffu, rsum1, 1);
    rsum1 += __shfl_xor_sync(0xffffffffu, rsum1, 2);
    const float inv0 = 1.f / rsum0, inv1 = 1.f / rsum1;

    __syncthreads();
    #pragma unroll
    for (int nt = 0; nt < 8; nt++) {
        int d = nt * 8 + 2 * tig;
        int q = wid * 16 + g;
        sO[d * 132 + q]           = o[nt][0] * inv0;
        sO[(d + 1) * 132 + q]     = o[nt][1] * inv0;
        sO[d * 132 + q + 8]       = o[nt][2] * inv1;
        sO[(d + 1) * 132 + q + 8] = o[nt][3] * inv1;
    }
    __syncthreads();

    const int b = bh >> 3, h = bh & 7;
    float* dst = g_att + ((size_t)b * C + h * 64) * NPIX;
    for (int idx = tid; idx < 64 * 128; idx += 256) {
        int d = idx >> 7, q = idx & 127;
        int n = n0 + q;
        if (n < NPIX) dst[(size_t)d * NPIX + n] = sO[d * 132 + q];
    }
}

// ======================= PE branch (unchanged) ==============================
__global__ __launch_bounds__(256) void pe_kernel(
    const float* __restrict__ pw,
    const float* __restrict__ gamma, const float* __restrict__ beta,
    const float* __restrict__ mean,  const float* __restrict__ var)
{
    __shared__ float img[NPIX];
    const int bc = blockIdx.x;
    const int b = bc >> 9;
    const int c = bc & 511;
    const int h = c >> 6, d = c & 63;
    const float* v = g_qkv + ((size_t)(b * NH + h) * (2 * KD + HD) + 2 * KD + d) * NPIX;
    const int tid = threadIdx.x;

    for (int l = tid; l < NPIX; l += 256) img[l] = v[l];

    float w[9];
    #pragma unroll
    for (int k = 0; k < 9; k++) w[k] = pw[c * 9 + k];
    float inv = gamma[c] * rsqrtf(var[c] + EPSV);
    float add = beta[c] - mean[c] * inv;
    __syncthreads();

    for (int l = tid; l < NPIX; l += 256) {
        int py = l / IW, px = l % IW;
        float s = 0.f;
        #pragma unroll
        for (int ky = 0; ky < 3; ky++) {
            int yy = py + ky - 1;
            if (yy < 0 || yy >= IH) continue;
            #pragma unroll
            for (int kx = 0; kx < 3; kx++) {
                int xx = px + kx - 1;
                if (xx < 0 || xx >= IW) continue;
                s += w[ky * 3 + kx] * img[yy * IW + xx];
            }
        }
        size_t idx = (size_t)bc * NPIX + l;
        g_y[idx] = s * inv + add + g_att[idx];
    }
}

// ============================================================================
extern "C" void kernel_launch(void* const* d_in, const int* in_sizes, int n_in,
                              void* d_out, int out_size)
{
    const float* x      = (const float*)d_in[0];
    const float* qkv_w  = (const float*)d_in[1];
    const float* qkv_g  = (const float*)d_in[2];
    const float* qkv_b  = (const float*)d_in[3];
    const float* qkv_m  = (const float*)d_in[4];
    const float* qkv_v  = (const float*)d_in[5];
    const float* pe_w   = (const float*)d_in[6];
    const float* pe_g   = (const float*)d_in[7];
    const float* pe_b   = (const float*)d_in[8];
    const float* pe_m   = (const float*)d_in[9];
    const float* pe_v   = (const float*)d_in[10];
    const float* proj_w = (const float*)d_in[11];
    const float* proj_g = (const float*)d_in[12];
    const float* proj_b = (const float*)d_in[13];
    const float* proj_m = (const float*)d_in[14];
    const float* proj_v = (const float*)d_in[15];
    float* out = (float*)d_out;

    float *qkv_buf, *y_buf;
    __nv_bfloat16 *wcq, *wcp, *xcb;
    cudaGetSymbolAddress((void**)&qkv_buf, g_qkv);
    cudaGetSymbolAddress((void**)&y_buf, g_y);
    cudaGetSymbolAddress((void**)&wcq, g_wcq);
    cudaGetSymbolAddress((void**)&wcp, g_wcp);
    cudaGetSymbolAddress((void**)&xcb, g_xc);

    // 0) operand prep (triple-bf16)
    prep_w<<<(HQKV * 512 + 255) / 256, 256>>>(qkv_w, wcq, HQKV * 512);
    prep_w<<<(C * 512 + 255) / 256, 256>>>(proj_w, wcp, C * 512);
    prep_xt<<<dim3(16, 50, B), 256>>>(x, xcb);

    // 1) qkv = BN(conv1x1(x, qkv_w))
    gemm3_bn<<<dim3(13, HQKV / 128, B), 256>>>(
        wcq, xcb, qkv_g, qkv_b, qkv_m, qkv_v, qkv_buf, HQKV);

    // 2) HMMA flash attention -> g_att
    attn_hmma_kernel<<<dim3(13, B * NH), 256>>>();

    // 3) g_y = BN(dwconv3x3(v)) + g_att
    pe_kernel<<<B * C, 256>>>(pe_w, pe_g, pe_b, pe_m, pe_v);

    // 3b) y -> triple-transposed bf16 (reuse g_xc)
    prep_xt<<<dim3(16, 50, B), 256>>>(y_buf, xcb);

    // 4) out = BN(conv1x1(y, proj_w))
    gemm3_bn<<<dim3(13, C / 128, B), 256>>>(
        wcp, xcb, proj_g, proj_b, proj_m, proj_v, out, C);
}

// round 6
// speedup vs baseline: 1.2287x; 1.2287x over previous
#include <cuda_runtime.h>
#include <cuda_bf16.h>
#include <cstdint>
#include <math.h>

#define EPSV 1e-5f
constexpr int B     = 8;
constexpr int C     = 512;
constexpr int NH    = 8;
constexpr int KD    = 32;
constexpr int HD    = 64;
constexpr int HQKV  = 1024;
constexpr int NPIX  = 1600;
constexpr int IH    = 40;
constexpr int IW    = 40;
constexpr int K3    = 1536;       // 3 * 512
constexpr float SCALE = 0.17677669529663687f;

__device__ __align__(16) float g_qkv[(size_t)B * HQKV * NPIX];
__device__ __align__(16) float g_att[(size_t)B * C * NPIX];
__device__ __align__(16) float g_y  [(size_t)B * C * NPIX];
__device__ __align__(16) __nv_bfloat16 g_wcq[(size_t)HQKV * K3];
__device__ __align__(16) __nv_bfloat16 g_wcp[(size_t)C * K3];
__device__ __align__(16) __nv_bfloat16 g_xc [(size_t)B * NPIX * K3];

// ===================== helpers =====================
__device__ __forceinline__ float bf_round(float x) {
    return __bfloat162float(__float2bfloat16_rn(x));
}
__device__ __forceinline__ uint32_t pack2(float hi, float lo) {
    uint32_t r;
    asm("cvt.rn.bf16x2.f32 %0, %1, %2;" : "=r"(r) : "f"(hi), "f"(lo));
    return r;
}
__device__ __forceinline__ void mma16816(float* c, const uint32_t* a, uint32_t b0, uint32_t b1) {
    asm volatile(
        "mma.sync.aligned.m16n8k16.row.col.f32.bf16.bf16.f32 "
        "{%0,%1,%2,%3}, {%4,%5,%6,%7}, {%8,%9}, {%0,%1,%2,%3};"
        : "+f"(c[0]), "+f"(c[1]), "+f"(c[2]), "+f"(c[3])
        : "r"(a[0]), "r"(a[1]), "r"(a[2]), "r"(a[3]), "r"(b0), "r"(b1));
}
__device__ __forceinline__ void cp16(uint32_t dst, const void* src) {
    asm volatile("cp.async.cg.shared.global [%0], [%1], 16;" :: "r"(dst), "l"(src));
}
#define CP_COMMIT() asm volatile("cp.async.commit_group;" ::: "memory")
#define CP_WAIT(n)  asm volatile("cp.async.wait_group %0;" :: "n"(n) : "memory")

// ================= prep: W -> triple bf16 [m][3k]: (h,h,l) ==================
__global__ __launch_bounds__(256) void prep_w(const float* __restrict__ W,
                                              __nv_bfloat16* __restrict__ out, int MK)
{
    int i = blockIdx.x * 256 + threadIdx.x;
    if (i >= MK) return;
    int m = i >> 9, k = i & 511;
    float v = W[i];
    float h = bf_round(v);
    __nv_bfloat16* d = out + (size_t)m * K3 + 3 * k;
    d[0] = __float2bfloat16_rn(h);
    d[1] = __float2bfloat16_rn(h);
    d[2] = __float2bfloat16_rn(v - h);
}

// ====== prep: X [b][k][n] -> triple bf16 [b][n][3k]: (h,l,h), vectorized ====
// Tile: 32 k x 64 n. Stage in smem [64 n][112 bf16] (96 used, 16B-aligned rows),
// then write 16B float4 chunks coalesced.
__global__ __launch_bounds__(256) void prep_xt(const float* __restrict__ X,
                                               __nv_bfloat16* __restrict__ out)
{
    __shared__ __align__(16) __nv_bfloat16 s[64 * 112];
    const int tid = threadIdx.x;
    const int k0 = blockIdx.x * 32, n0 = blockIdx.y * 64, b = blockIdx.z;
    const float* Xb = X + (size_t)b * 512 * NPIX;

    #pragma unroll
    for (int i = 0; i < 8; i++) {
        int idx = tid + i * 256;
        int k = idx >> 6, n = idx & 63;
        float v = Xb[(size_t)(k0 + k) * NPIX + n0 + n];
        float h = bf_round(v);
        __nv_bfloat16 hb = __float2bfloat16_rn(h);
        s[n * 112 + 3 * k]     = hb;
        s[n * 112 + 3 * k + 1] = __float2bfloat16_rn(v - h);
        s[n * 112 + 3 * k + 2] = hb;
    }
    __syncthreads();

    __nv_bfloat16* dst = out + (size_t)b * NPIX * K3 + (size_t)n0 * K3 + k0 * 3;
    #pragma unroll
    for (int i = 0; i < 3; i++) {
        int c = tid + i * 256;            // 768 chunks = 64 rows x 12
        int row = c / 12, col = c % 12;
        float4 val = *(const float4*)&s[row * 112 + col * 8];
        *(float4*)(dst + (size_t)row * K3 + col * 8) = val;
    }
}

// ============== pipelined bf16 GEMM (K'=1536) + fused BN ====================
// CTA 128m x 128n, 8 warps (4M x 2N), K-chunk 64, cp.async double buffer.
constexpr int KC  = 64;
constexpr int NIT = K3 / KC;                   // 24
constexpr int STG = 128 * 72 * 2;              // bytes per operand tile (18432)
constexpr int STAGE = 2 * STG;                 // W + X per stage (36864)
constexpr int GSMEM = 2 * STAGE;               // 73728

__global__ __launch_bounds__(256, 2) void gemm3_bn(
    const __nv_bfloat16* __restrict__ wc, const __nv_bfloat16* __restrict__ xc,
    const float* __restrict__ gamma, const float* __restrict__ beta,
    const float* __restrict__ mean,  const float* __restrict__ var,
    float* __restrict__ out, int M)
{
    extern __shared__ __align__(16) char dsm[];
    __shared__ float sbn[128][2];

    const int tid  = threadIdx.x;
    const int wid  = tid >> 5;
    const int lane = tid & 31;
    const int g    = lane >> 2;
    const int tig  = lane & 3;
    const int wm   = wid >> 1;
    const int wn   = wid & 1;
    const int n0   = blockIdx.x * 128;
    const int m0   = blockIdx.y * 128;
    const int b    = blockIdx.z;
    const __nv_bfloat16* xb = xc + (size_t)b * NPIX * K3;

    if (tid < 128) {
        int m = m0 + tid;
        float inv = gamma[m] * rsqrtf(var[m] + EPSV);
        sbn[tid][0] = inv;
        sbn[tid][1] = beta[m] - mean[m] * inv;
    }

    const uint32_t sb = (uint32_t)__cvta_generic_to_shared(dsm);

    // cp.async assignment: 1024 chunks per operand (128 rows x 8 segs), 4/thread
    int rowL[4], segL[4], nCl[4];
    #pragma unroll
    for (int j = 0; j < 4; j++) {
        int id = tid + j * 256;
        rowL[j] = id >> 3; segL[j] = id & 7;
        int n = n0 + rowL[j]; if (n > NPIX - 1) n = NPIX - 1;
        nCl[j] = n;
    }

    float acc[2][8][4];
    #pragma unroll
    for (int i = 0; i < 2; i++)
        #pragma unroll
        for (int j = 0; j < 8; j++)
            #pragma unroll
            for (int l = 0; l < 4; l++) acc[i][j][l] = 0.f;

    auto issue = [&](int buf, int k0) {
        uint32_t bo = sb + buf * STAGE;
        #pragma unroll
        for (int j = 0; j < 4; j++) {
            uint32_t d = rowL[j] * 144 + segL[j] * 16;
            cp16(bo + d,       wc + (size_t)(m0 + rowL[j]) * K3 + k0 + segL[j] * 8);
            cp16(bo + STG + d, xb + (size_t)nCl[j] * K3 + k0 + segL[j] * 8);
        }
    };

    issue(0, 0); CP_COMMIT();
    int buf = 0;
    #pragma unroll 1
    for (int it = 0; it < NIT; it++) {
        if (it + 1 < NIT) { issue(buf ^ 1, (it + 1) * KC); CP_COMMIT(); CP_WAIT(1); }
        else              { CP_WAIT(0); }
        __syncthreads();

        const __nv_bfloat16* w_s = (const __nv_bfloat16*)(dsm + buf * STAGE);
        const __nv_bfloat16* x_s = (const __nv_bfloat16*)(dsm + buf * STAGE + STG);
        #pragma unroll
        for (int ks = 0; ks < 4; ks++) {
            const int cb = ks * 16 + 2 * tig;
            uint32_t aW[2][4];
            #pragma unroll
            for (int mf = 0; mf < 2; mf++) {
                int r0 = wm * 32 + mf * 16 + g;
                aW[mf][0] = *(const uint32_t*)&w_s[r0 * 72 + cb];
                aW[mf][1] = *(const uint32_t*)&w_s[(r0 + 8) * 72 + cb];
                aW[mf][2] = *(const uint32_t*)&w_s[r0 * 72 + cb + 8];
                aW[mf][3] = *(const uint32_t*)&w_s[(r0 + 8) * 72 + cb + 8];
            }
            #pragma unroll
            for (int nf = 0; nf < 8; nf++) {
                int nr = wn * 64 + nf * 8 + g;
                uint32_t b0 = *(const uint32_t*)&x_s[nr * 72 + cb];
                uint32_t b1 = *(const uint32_t*)&x_s[nr * 72 + cb + 8];
                mma16816(acc[0][nf], aW[0], b0, b1);
                mma16816(acc[1][nf], aW[1], b0, b1);
            }
        }
        __syncthreads();
        buf ^= 1;
    }

    // ---- epilogue: BN + store ----
    #pragma unroll
    for (int mf = 0; mf < 2; mf++) {
        int mla = wm * 32 + mf * 16 + g;
        int mlb = mla + 8;
        float inva = sbn[mla][0], adda = sbn[mla][1];
        float invb = sbn[mlb][0], addb = sbn[mlb][1];
        float* rowa = out + ((size_t)b * M + m0 + mla) * NPIX;
        float* rowb = out + ((size_t)b * M + m0 + mlb) * NPIX;
        #pragma unroll
        for (int nf = 0; nf < 8; nf++) {
            int n = n0 + wn * 64 + nf * 8 + 2 * tig;
            if (n < NPIX) {
                *(float2*)&rowa[n] = make_float2(acc[mf][nf][0] * inva + adda,
                                                 acc[mf][nf][1] * inva + adda);
                *(float2*)&rowb[n] = make_float2(acc[mf][nf][2] * invb + addb,
                                                 acc[mf][nf][3] * invb + addb);
            }
        }
    }
}

// ============ FlashAttention-2 style HMMA attention (unchanged) =============
constexpr int SQH = 0, SQL = 9216, SKH = 18432, SKL = 23040, SVH = 27648, SVL = 36864;

__global__ __launch_bounds__(256) void attn_hmma_kernel()
{
    __shared__ __align__(16) char sm[46080];
    __nv_bfloat16* qh = (__nv_bfloat16*)(sm + SQH);
    __nv_bfloat16* ql = (__nv_bfloat16*)(sm + SQL);
    __nv_bfloat16* kh = (__nv_bfloat16*)(sm + SKH);
    __nv_bfloat16* kl = (__nv_bfloat16*)(sm + SKL);
    __nv_bfloat16* vh = (__nv_bfloat16*)(sm + SVH);
    __nv_bfloat16* vl = (__nv_bfloat16*)(sm + SVL);
    float* sO = (float*)sm;

    const int tid  = threadIdx.x;
    const int wid  = tid >> 5;
    const int lane = tid & 31;
    const int g    = lane >> 2;
    const int tig  = lane & 3;
    const int bh   = blockIdx.y;
    const int n0   = blockIdx.x * 128;

    const float* qp = g_qkv + (size_t)bh * 128 * NPIX;
    const float* kp = qp + (size_t)KD * NPIX;
    const float* vp = qp + (size_t)2 * KD * NPIX;

    for (int idx = tid; idx < 128 * 32; idx += 256) {
        int c = idx >> 7, q = idx & 127;
        int n = n0 + q; if (n > NPIX - 1) n = NPIX - 1;
        float v = qp[(size_t)c * NPIX + n] * SCALE;
        float h = bf_round(v);
        qh[q * 36 + c] = __float2bfloat16_rn(h);
        ql[q * 36 + c] = __float2bfloat16_rn(v - h);
    }
    __syncthreads();

    uint32_t aQh[2][4], aQl[2][4];
    {
        int r0 = wid * 16 + g;
        #pragma unroll
        for (int ks = 0; ks < 2; ks++) {
            int cb = ks * 16 + 2 * tig;
            aQh[ks][0] = *(const uint32_t*)&qh[r0 * 36 + cb];
            aQh[ks][1] = *(const uint32_t*)&qh[(r0 + 8) * 36 + cb];
            aQh[ks][2] = *(const uint32_t*)&qh[r0 * 36 + cb + 8];
            aQh[ks][3] = *(const uint32_t*)&qh[(r0 + 8) * 36 + cb + 8];
            aQl[ks][0] = *(const uint32_t*)&ql[r0 * 36 + cb];
            aQl[ks][1] = *(const uint32_t*)&ql[(r0 + 8) * 36 + cb];
            aQl[ks][2] = *(const uint32_t*)&ql[r0 * 36 + cb + 8];
            aQl[ks][3] = *(const uint32_t*)&ql[(r0 + 8) * 36 + cb + 8];
        }
    }

    float o[8][4];
    #pragma unroll
    for (int i = 0; i < 8; i++)
        #pragma unroll
        for (int j = 0; j < 4; j++) o[i][j] = 0.f;
    float rsum0 = 0.f, rsum1 = 0.f;

    for (int t = 0; t < 25; t++) {
        const int m0 = t * 64;
        __syncthreads();
        for (int idx = tid; idx < 64 * 32; idx += 256) {
            int c = idx >> 6, k = idx & 63;
            float v = kp[(size_t)c * NPIX + m0 + k];
            float h = bf_round(v);
            kh[k * 36 + c] = __float2bfloat16_rn(h);
            kl[k * 36 + c] = __float2bfloat16_rn(v - h);
        }
        for (int idx = tid; idx < 64 * 64; idx += 256) {
            int d = idx >> 6, k = idx & 63;
            float v = vp[(size_t)d * NPIX + m0 + k];
            float h = bf_round(v);
            vh[d * 72 + k] = __float2bfloat16_rn(h);
            vl[d * 72 + k] = __float2bfloat16_rn(v - h);
        }
        __syncthreads();

        float s[8][4];
        #pragma unroll
        for (int nt = 0; nt < 8; nt++) {
            s[nt][0] = s[nt][1] = s[nt][2] = s[nt][3] = 0.f;
            #pragma unroll
            for (int ks = 0; ks < 2; ks++) {
                int key = nt * 8 + g;
                int cb  = ks * 16 + 2 * tig;
                uint32_t bh0 = *(const uint32_t*)&kh[key * 36 + cb];
                uint32_t bh1 = *(const uint32_t*)&kh[key * 36 + cb + 8];
                uint32_t bl0 = *(const uint32_t*)&kl[key * 36 + cb];
                uint32_t bl1 = *(const uint32_t*)&kl[key * 36 + cb + 8];
                mma16816(s[nt], aQh[ks], bh0, bh1);
                mma16816(s[nt], aQh[ks], bl0, bl1);
                mma16816(s[nt], aQl[ks], bh0, bh1);
            }
        }

        #pragma unroll
        for (int nt = 0; nt < 8; nt++) {
            s[nt][0] = __expf(s[nt][0]);
            s[nt][1] = __expf(s[nt][1]);
            s[nt][2] = __expf(s[nt][2]);
            s[nt][3] = __expf(s[nt][3]);
            rsum0 += s[nt][0] + s[nt][1];
            rsum1 += s[nt][2] + s[nt][3];
        }

        #pragma unroll
        for (int ks = 0; ks < 4; ks++) {
            const int ta = 2 * ks, tb_ = 2 * ks + 1;
            uint32_t ah[4], al[4];
            {
                float p0 = s[ta][0],  p1 = s[ta][1];
                float h0 = bf_round(p0), h1 = bf_round(p1);
                ah[0] = pack2(h1, h0); al[0] = pack2(p1 - h1, p0 - h0);
                p0 = s[ta][2]; p1 = s[ta][3];
                h0 = bf_round(p0); h1 = bf_round(p1);
                ah[1] = pack2(h1, h0); al[1] = pack2(p1 - h1, p0 - h0);
                p0 = s[tb_][0]; p1 = s[tb_][1];
                h0 = bf_round(p0); h1 = bf_round(p1);
                ah[2] = pack2(h1, h0); al[2] = pack2(p1 - h1, p0 - h0);
                p0 = s[tb_][2]; p1 = s[tb_][3];
                h0 = bf_round(p0); h1 = bf_round(p1);
                ah[3] = pack2(h1, h0); al[3] = pack2(p1 - h1, p0 - h0);
            }
            #pragma unroll
            for (int nt = 0; nt < 8; nt++) {
                int d  = nt * 8 + g;
                int kb = ks * 16 + 2 * tig;
                uint32_t bh0 = *(const uint32_t*)&vh[d * 72 + kb];
                uint32_t bh1 = *(const uint32_t*)&vh[d * 72 + kb + 8];
                uint32_t bl0 = *(const uint32_t*)&vl[d * 72 + kb];
                uint32_t bl1 = *(const uint32_t*)&vl[d * 72 + kb + 8];
                mma16816(o[nt], ah, bh0, bh1);
                mma16816(o[nt], ah, bl0, bl1);
                mma16816(o[nt], al, bh0, bh1);
            }
        }
    }

    rsum0 += __shfl_xor_sync(0xffffffffu, rsum0, 1);
    rsum0 += __shfl_xor_sync(0xffffffffu, rsum0, 2);
    rsum1 += __shfl_xor_sync(0xffffffffu, rsum1, 1);
    rsum1 += __shfl_xor_sync(0xffffffffu, rsum1, 2);
    const float inv0 = 1.f / rsum0, inv1 = 1.f / rsum1;

    __syncthreads();
    #pragma unroll
    for (int nt = 0; nt < 8; nt++) {
        int d = nt * 8 + 2 * tig;
        int q = wid * 16 + g;
        sO[d * 132 + q]           = o[nt][0] * inv0;
        sO[(d + 1) * 132 + q]     = o[nt][1] * inv0;
        sO[d * 132 + q + 8]       = o[nt][2] * inv1;
        sO[(d + 1) * 132 + q + 8] = o[nt][3] * inv1;
    }
    __syncthreads();

    const int b = bh >> 3, h = bh & 7;
    float* dst = g_att + ((size_t)b * C + h * 64) * NPIX;
    for (int idx = tid; idx < 64 * 128; idx += 256) {
        int d = idx >> 7, q = idx & 127;
        int n = n0 + q;
        if (n < NPIX) dst[(size_t)d * NPIX + n] = sO[d * 132 + q];
    }
}

// ======================= PE branch (unchanged) ==============================
__global__ __launch_bounds__(256) void pe_kernel(
    const float* __restrict__ pw,
    const float* __restrict__ gamma, const float* __restrict__ beta,
    const float* __restrict__ mean,  const float* __restrict__ var)
{
    __shared__ float img[NPIX];
    const int bc = blockIdx.x;
    const int b = bc >> 9;
    const int c = bc & 511;
    const int h = c >> 6, d = c & 63;
    const float* v = g_qkv + ((size_t)(b * NH + h) * (2 * KD + HD) + 2 * KD + d) * NPIX;
    const int tid = threadIdx.x;

    for (int l = tid; l < NPIX; l += 256) img[l] = v[l];

    float w[9];
    #pragma unroll
    for (int k = 0; k < 9; k++) w[k] = pw[c * 9 + k];
    float inv = gamma[c] * rsqrtf(var[c] + EPSV);
    float add = beta[c] - mean[c] * inv;
    __syncthreads();

    for (int l = tid; l < NPIX; l += 256) {
        int py = l / IW, px = l % IW;
        float s = 0.f;
        #pragma unroll
        for (int ky = 0; ky < 3; ky++) {
            int yy = py + ky - 1;
            if (yy < 0 || yy >= IH) continue;
            #pragma unroll
            for (int kx = 0; kx < 3; kx++) {
                int xx = px + kx - 1;
                if (xx < 0 || xx >= IW) continue;
                s += w[ky * 3 + kx] * img[yy * IW + xx];
            }
        }
        size_t idx = (size_t)bc * NPIX + l;
        g_y[idx] = s * inv + add + g_att[idx];
    }
}

// ============================================================================
extern "C" void kernel_launch(void* const* d_in, const int* in_sizes, int n_in,
                              void* d_out, int out_size)
{
    const float* x      = (const float*)d_in[0];
    const float* qkv_w  = (const float*)d_in[1];
    const float* qkv_g  = (const float*)d_in[2];
    const float* qkv_b  = (const float*)d_in[3];
    const float* qkv_m  = (const float*)d_in[4];
    const float* qkv_v  = (const float*)d_in[5];
    const float* pe_w   = (const float*)d_in[6];
    const float* pe_g   = (const float*)d_in[7];
    const float* pe_b   = (const float*)d_in[8];
    const float* pe_m   = (const float*)d_in[9];
    const float* pe_v   = (const float*)d_in[10];
    const float* proj_w = (const float*)d_in[11];
    const float* proj_g = (const float*)d_in[12];
    const float* proj_b = (const float*)d_in[13];
    const float* proj_m = (const float*)d_in[14];
    const float* proj_v = (const float*)d_in[15];
    float* out = (float*)d_out;

    float *qkv_buf, *y_buf;
    __nv_bfloat16 *wcq, *wcp, *xcb;
    cudaGetSymbolAddress((void**)&qkv_buf, g_qkv);
    cudaGetSymbolAddress((void**)&y_buf, g_y);
    cudaGetSymbolAddress((void**)&wcq, g_wcq);
    cudaGetSymbolAddress((void**)&wcp, g_wcp);
    cudaGetSymbolAddress((void**)&xcb, g_xc);

    cudaFuncSetAttribute(gemm3_bn, cudaFuncAttributeMaxDynamicSharedMemorySize, GSMEM);

    // 0) operand prep (triple-bf16)
    prep_w<<<(HQKV * 512 + 255) / 256, 256>>>(qkv_w, wcq, HQKV * 512);
    prep_w<<<(C * 512 + 255) / 256, 256>>>(proj_w, wcp, C * 512);
    prep_xt<<<dim3(16, 25, B), 256>>>(x, xcb);

    // 1) qkv = BN(conv1x1(x, qkv_w))
    gemm3_bn<<<dim3(13, HQKV / 128, B), 256, GSMEM>>>(
        wcq, xcb, qkv_g, qkv_b, qkv_m, qkv_v, qkv_buf, HQKV);

    // 2) HMMA flash attention -> g_att
    attn_hmma_kernel<<<dim3(13, B * NH), 256>>>();

    // 3) g_y = BN(dwconv3x3(v)) + g_att
    pe_kernel<<<B * C, 256>>>(pe_w, pe_g, pe_b, pe_m, pe_v);

    // 3b) y -> triple bf16 (reuse g_xc)
    prep_xt<<<dim3(16, 25, B), 256>>>(y_buf, xcb);

    // 4) out = BN(conv1x1(y, proj_w))
    gemm3_bn<<<dim3(13, C / 128, B), 256, GSMEM>>>(
        wcp, xcb, proj_g, proj_b, proj_m, proj_v, out, C);
}

// round 7
// speedup vs baseline: 1.3330x; 1.0849x over previous
#include <cuda_runtime.h>
#include <cuda_bf16.h>
#include <cstdint>
#include <math.h>

#define EPSV 1e-5f
constexpr int B     = 8;
constexpr int C     = 512;
constexpr int NH    = 8;
constexpr int KD    = 32;
constexpr int HD    = 64;
constexpr int HQKV  = 1024;
constexpr int NPIX  = 1600;
constexpr int IH    = 40;
constexpr int IW    = 40;
constexpr int K3    = 1536;
constexpr float SCALE = 0.17677669529663687f;

__device__ __align__(16) float g_qkv[(size_t)B * HQKV * NPIX];
__device__ __align__(16) float g_att[(size_t)B * C * NPIX];
__device__ __align__(16) float g_y  [(size_t)B * C * NPIX];
__device__ __align__(16) __nv_bfloat16 g_wcq[(size_t)HQKV * K3];
__device__ __align__(16) __nv_bfloat16 g_wcp[(size_t)C * K3];
__device__ __align__(16) __nv_bfloat16 g_xc [(size_t)B * NPIX * K3];
// attention prepped operands
__device__ __align__(16) __nv_bfloat16 g_qt[(size_t)64 * 1664 * 96];  // (qh,qh,ql)*SCALE
__device__ __align__(16) __nv_bfloat16 g_kt[(size_t)64 * 1600 * 96];  // (kh,kl,kh)
__device__ __align__(16) __nv_bfloat16 g_vh[(size_t)64 * 64 * 1600];
__device__ __align__(16) __nv_bfloat16 g_vl[(size_t)64 * 64 * 1600];

// ===================== helpers =====================
__device__ __forceinline__ float bf_round(float x) {
    return __bfloat162float(__float2bfloat16_rn(x));
}
__device__ __forceinline__ uint32_t pack2(float hi, float lo) {
    uint32_t r;
    asm("cvt.rn.bf16x2.f32 %0, %1, %2;" : "=r"(r) : "f"(hi), "f"(lo));
    return r;
}
__device__ __forceinline__ void mma16816(float* c, const uint32_t* a, uint32_t b0, uint32_t b1) {
    asm volatile(
        "mma.sync.aligned.m16n8k16.row.col.f32.bf16.bf16.f32 "
        "{%0,%1,%2,%3}, {%4,%5,%6,%7}, {%8,%9}, {%0,%1,%2,%3};"
        : "+f"(c[0]), "+f"(c[1]), "+f"(c[2]), "+f"(c[3])
        : "r"(a[0]), "r"(a[1]), "r"(a[2]), "r"(a[3]), "r"(b0), "r"(b1));
}
__device__ __forceinline__ void cp16(uint32_t dst, const void* src) {
    asm volatile("cp.async.cg.shared.global [%0], [%1], 16;" :: "r"(dst), "l"(src));
}
#define CP_COMMIT() asm volatile("cp.async.commit_group;" ::: "memory")
#define CP_WAIT(n)  asm volatile("cp.async.wait_group %0;" :: "n"(n) : "memory")

// ================= prep: W -> triple bf16 [m][3k]: (h,h,l) ==================
__global__ __launch_bounds__(256) void prep_w(const float* __restrict__ W,
                                              __nv_bfloat16* __restrict__ out, int MK)
{
    int i = blockIdx.x * 256 + threadIdx.x;
    if (i >= MK) return;
    int m = i >> 9, k = i & 511;
    float v = W[i];
    float h = bf_round(v);
    __nv_bfloat16* d = out + (size_t)m * K3 + 3 * k;
    d[0] = __float2bfloat16_rn(h);
    d[1] = __float2bfloat16_rn(h);
    d[2] = __float2bfloat16_rn(v - h);
}

// ====== prep: X [b][k][n] -> triple bf16 [b][n][3k]: (h,l,h), vectorized ====
__global__ __launch_bounds__(256) void prep_xt(const float* __restrict__ X,
                                               __nv_bfloat16* __restrict__ out)
{
    __shared__ __align__(16) __nv_bfloat16 s[64 * 112];
    const int tid = threadIdx.x;
    const int k0 = blockIdx.x * 32, n0 = blockIdx.y * 64, b = blockIdx.z;
    const float* Xb = X + (size_t)b * 512 * NPIX;

    #pragma unroll
    for (int i = 0; i < 8; i++) {
        int idx = tid + i * 256;
        int k = idx >> 6, n = idx & 63;
        float v = Xb[(size_t)(k0 + k) * NPIX + n0 + n];
        float h = bf_round(v);
        __nv_bfloat16 hb = __float2bfloat16_rn(h);
        s[n * 112 + 3 * k]     = hb;
        s[n * 112 + 3 * k + 1] = __float2bfloat16_rn(v - h);
        s[n * 112 + 3 * k + 2] = hb;
    }
    __syncthreads();

    __nv_bfloat16* dst = out + (size_t)b * NPIX * K3 + (size_t)n0 * K3 + k0 * 3;
    #pragma unroll
    for (int i = 0; i < 3; i++) {
        int c = tid + i * 256;
        int row = c / 12, col = c % 12;
        float4 val = *(const float4*)&s[row * 112 + col * 8];
        *(float4*)(dst + (size_t)row * K3 + col * 8) = val;
    }
}

// ===== prep: q,k of g_qkv -> Qt[bh][n][96], Kt[bh][k][96] triples ===========
__global__ __launch_bounds__(256) void prep_qk()
{
    __shared__ __align__(16) __nv_bfloat16 sq[64 * 104];
    __shared__ __align__(16) __nv_bfloat16 sk[64 * 104];
    const int tid = threadIdx.x;
    const int n0 = blockIdx.x * 64;
    const int bh = blockIdx.y;
    const float* qp = g_qkv + (size_t)bh * 128 * NPIX;
    const float* kp = qp + (size_t)KD * NPIX;

    #pragma unroll
    for (int i = 0; i < 8; i++) {
        int idx = tid + i * 256;
        int c = idx >> 6, n = idx & 63;
        float v = qp[(size_t)c * NPIX + n0 + n] * SCALE;
        float h = bf_round(v);
        __nv_bfloat16 hb = __float2bfloat16_rn(h);
        sq[n * 104 + 3 * c]     = hb;
        sq[n * 104 + 3 * c + 1] = hb;
        sq[n * 104 + 3 * c + 2] = __float2bfloat16_rn(v - h);
        float v2 = kp[(size_t)c * NPIX + n0 + n];
        float h2 = bf_round(v2);
        __nv_bfloat16 hb2 = __float2bfloat16_rn(h2);
        sk[n * 104 + 3 * c]     = hb2;
        sk[n * 104 + 3 * c + 1] = __float2bfloat16_rn(v2 - h2);
        sk[n * 104 + 3 * c + 2] = hb2;
    }
    __syncthreads();

    __nv_bfloat16* qd = g_qt + ((size_t)bh * 1664 + n0) * 96;
    __nv_bfloat16* kd = g_kt + ((size_t)bh * 1600 + n0) * 96;
    #pragma unroll
    for (int i = 0; i < 3; i++) {
        int c = tid + i * 256;             // 768 = 64 rows x 12 chunks
        int row = c / 12, seg = c % 12;
        *(float4*)(qd + (size_t)row * 96 + seg * 8) = *(const float4*)&sq[row * 104 + seg * 8];
        *(float4*)(kd + (size_t)row * 96 + seg * 8) = *(const float4*)&sk[row * 104 + seg * 8];
    }
}

// ===== prep: v of g_qkv -> Vh/Vl bf16 planes [bh][d][1600] ==================
__global__ __launch_bounds__(256) void prep_v()
{
    int i = blockIdx.x * 256 + threadIdx.x;      // 1,638,400 float4s total
    int bh = i / 25600;
    int r  = i % 25600;
    int d  = r / 400;
    int n  = (r % 400) * 4;
    const float* src = g_qkv + (size_t)bh * 128 * NPIX + (size_t)(2 * KD + d) * NPIX + n;
    float4 v = *(const float4*)src;
    float hx = bf_round(v.x), hy = bf_round(v.y), hz = bf_round(v.z), hw = bf_round(v.w);
    uint2 hi = make_uint2(pack2(hy, hx), pack2(hw, hz));
    uint2 lo = make_uint2(pack2(v.y - hy, v.x - hx), pack2(v.w - hw, v.z - hz));
    size_t o = ((size_t)bh * 64 + d) * 1600 + n;
    *(uint2*)(g_vh + o) = hi;
    *(uint2*)(g_vl + o) = lo;
}

// ============== pipelined bf16 GEMM (K'=1536) + fused BN ====================
constexpr int KC  = 64;
constexpr int NIT = K3 / KC;
constexpr int STG = 128 * 72 * 2;
constexpr int STAGE = 2 * STG;
constexpr int GSMEM = 2 * STAGE;

__global__ __launch_bounds__(256, 2) void gemm3_bn(
    const __nv_bfloat16* __restrict__ wc, const __nv_bfloat16* __restrict__ xc,
    const float* __restrict__ gamma, const float* __restrict__ beta,
    const float* __restrict__ mean,  const float* __restrict__ var,
    float* __restrict__ out, int M)
{
    extern __shared__ __align__(16) char dsm[];
    __shared__ float sbn[128][2];

    const int tid  = threadIdx.x;
    const int wid  = tid >> 5;
    const int lane = tid & 31;
    const int g    = lane >> 2;
    const int tig  = lane & 3;
    const int wm   = wid >> 1;
    const int wn   = wid & 1;
    const int n0   = blockIdx.x * 128;
    const int m0   = blockIdx.y * 128;
    const int b    = blockIdx.z;
    const __nv_bfloat16* xb = xc + (size_t)b * NPIX * K3;

    if (tid < 128) {
        int m = m0 + tid;
        float inv = gamma[m] * rsqrtf(var[m] + EPSV);
        sbn[tid][0] = inv;
        sbn[tid][1] = beta[m] - mean[m] * inv;
    }

    const uint32_t sb = (uint32_t)__cvta_generic_to_shared(dsm);

    int rowL[4], segL[4], nCl[4];
    #pragma unroll
    for (int j = 0; j < 4; j++) {
        int id = tid + j * 256;
        rowL[j] = id >> 3; segL[j] = id & 7;
        int n = n0 + rowL[j]; if (n > NPIX - 1) n = NPIX - 1;
        nCl[j] = n;
    }

    float acc[2][8][4];
    #pragma unroll
    for (int i = 0; i < 2; i++)
        #pragma unroll
        for (int j = 0; j < 8; j++)
            #pragma unroll
            for (int l = 0; l < 4; l++) acc[i][j][l] = 0.f;

    auto issue = [&](int buf, int k0) {
        uint32_t bo = sb + buf * STAGE;
        #pragma unroll
        for (int j = 0; j < 4; j++) {
            uint32_t d = rowL[j] * 144 + segL[j] * 16;
            cp16(bo + d,       wc + (size_t)(m0 + rowL[j]) * K3 + k0 + segL[j] * 8);
            cp16(bo + STG + d, xb + (size_t)nCl[j] * K3 + k0 + segL[j] * 8);
        }
    };

    issue(0, 0); CP_COMMIT();
    int buf = 0;
    #pragma unroll 1
    for (int it = 0; it < NIT; it++) {
        if (it + 1 < NIT) { issue(buf ^ 1, (it + 1) * KC); CP_COMMIT(); CP_WAIT(1); }
        else              { CP_WAIT(0); }
        __syncthreads();

        const __nv_bfloat16* w_s = (const __nv_bfloat16*)(dsm + buf * STAGE);
        const __nv_bfloat16* x_s = (const __nv_bfloat16*)(dsm + buf * STAGE + STG);
        #pragma unroll
        for (int ks = 0; ks < 4; ks++) {
            const int cb = ks * 16 + 2 * tig;
            uint32_t aW[2][4];
            #pragma unroll
            for (int mf = 0; mf < 2; mf++) {
                int r0 = wm * 32 + mf * 16 + g;
                aW[mf][0] = *(const uint32_t*)&w_s[r0 * 72 + cb];
                aW[mf][1] = *(const uint32_t*)&w_s[(r0 + 8) * 72 + cb];
                aW[mf][2] = *(const uint32_t*)&w_s[r0 * 72 + cb + 8];
                aW[mf][3] = *(const uint32_t*)&w_s[(r0 + 8) * 72 + cb + 8];
            }
            #pragma unroll
            for (int nf = 0; nf < 8; nf++) {
                int nr = wn * 64 + nf * 8 + g;
                uint32_t b0 = *(const uint32_t*)&x_s[nr * 72 + cb];
                uint32_t b1 = *(const uint32_t*)&x_s[nr * 72 + cb + 8];
                mma16816(acc[0][nf], aW[0], b0, b1);
                mma16816(acc[1][nf], aW[1], b0, b1);
            }
        }
        __syncthreads();
        buf ^= 1;
    }

    #pragma unroll
    for (int mf = 0; mf < 2; mf++) {
        int mla = wm * 32 + mf * 16 + g;
        int mlb = mla + 8;
        float inva = sbn[mla][0], adda = sbn[mla][1];
        float invb = sbn[mlb][0], addb = sbn[mlb][1];
        float* rowa = out + ((size_t)b * M + m0 + mla) * NPIX;
        float* rowb = out + ((size_t)b * M + m0 + mlb) * NPIX;
        #pragma unroll
        for (int nf = 0; nf < 8; nf++) {
            int n = n0 + wn * 64 + nf * 8 + 2 * tig;
            if (n < NPIX) {
                *(float2*)&rowa[n] = make_float2(acc[mf][nf][0] * inva + adda,
                                                 acc[mf][nf][1] * inva + adda);
                *(float2*)&rowb[n] = make_float2(acc[mf][nf][2] * invb + addb,
                                                 acc[mf][nf][3] * invb + addb);
            }
        }
    }
}

// ============ attention v2: prepped operands + cp.async pipeline ============
// smem layout (bytes):
//   sQ     @ 0      : 128 x 104 bf16 = 26624
//   K[s]   @ 26624 + s*13312 : 64 x 104 bf16
//   Vh[s]  @ 53248 + s*18432 : 64 x 72 bf16 ; Vl at +9216
//   sO (epilogue alias @0)   : 64 x 132 f32 = 33792
constexpr int ASM_K0 = 26624;
constexpr int ASM_V0 = 53248;
constexpr int ASMEM  = 90112;

__global__ __launch_bounds__(256, 2) void attn2_kernel()
{
    extern __shared__ __align__(16) char sm[];
    const uint32_t sb = (uint32_t)__cvta_generic_to_shared(sm);
    const __nv_bfloat16* sQ = (const __nv_bfloat16*)sm;
    float* sO = (float*)sm;

    const int tid  = threadIdx.x;
    const int wid  = tid >> 5;
    const int lane = tid & 31;
    const int g    = lane >> 2;
    const int tig  = lane & 3;
    const int bh   = blockIdx.y;
    const int q0   = blockIdx.x * 128;

    const __nv_bfloat16* qt  = g_qt + (size_t)bh * 1664 * 96;
    const __nv_bfloat16* kt  = g_kt + (size_t)bh * 1600 * 96;
    const __nv_bfloat16* vhp = g_vh + (size_t)bh * 64 * 1600;
    const __nv_bfloat16* vlp = g_vl + (size_t)bh * 64 * 1600;

    // K/V chunk assignment
    const int krow = tid >> 2;               // reuse per j via offsets below
    (void)krow;

    auto issueKV = [&](int buf, int t) {
        uint32_t kb = sb + ASM_K0 + buf * 13312;
        #pragma unroll
        for (int j = 0; j < 3; j++) {        // K: 768 chunks
            int id = tid + j * 256;
            int row = id / 12, seg = id % 12;
            cp16(kb + row * 208 + seg * 16, kt + ((size_t)(t * 64 + row)) * 96 + seg * 8);
        }
        uint32_t vb = sb + ASM_V0 + buf * 18432;
        #pragma unroll
        for (int j = 0; j < 4; j++) {        // V: 1024 chunks (hi 512 + lo 512)
            int id = tid + j * 256;
            int half = id >> 9, r = id & 511;
            int row = r >> 3, seg = r & 7;
            const __nv_bfloat16* src = (half ? vlp : vhp) + (size_t)row * 1600 + t * 64 + seg * 8;
            cp16(vb + half * 9216 + row * 144 + seg * 16, src);
        }
    };

    // issue Q (one-time) + tile 0 as the first group
    #pragma unroll
    for (int j = 0; j < 6; j++) {
        int id = tid + j * 256;
        int row = id / 12, seg = id % 12;
        cp16(sb + row * 208 + seg * 16, qt + (size_t)(q0 + row) * 96 + seg * 8);
    }
    issueKV(0, 0);
    CP_COMMIT();

    uint32_t aQ[6][4];
    float o[8][4];
    #pragma unroll
    for (int i = 0; i < 8; i++)
        #pragma unroll
        for (int j = 0; j < 4; j++) o[i][j] = 0.f;
    float rsum0 = 0.f, rsum1 = 0.f;

    int buf = 0;
    #pragma unroll 1
    for (int t = 0; t < 25; t++) {
        if (t + 1 < 25) { issueKV(buf ^ 1, t + 1); CP_COMMIT(); CP_WAIT(1); }
        else            { CP_WAIT(0); }
        __syncthreads();

        if (t == 0) {
            int r0 = wid * 16 + g;
            #pragma unroll
            for (int ks = 0; ks < 6; ks++) {
                int cb = ks * 16 + 2 * tig;
                aQ[ks][0] = *(const uint32_t*)&sQ[r0 * 104 + cb];
                aQ[ks][1] = *(const uint32_t*)&sQ[(r0 + 8) * 104 + cb];
                aQ[ks][2] = *(const uint32_t*)&sQ[r0 * 104 + cb + 8];
                aQ[ks][3] = *(const uint32_t*)&sQ[(r0 + 8) * 104 + cb + 8];
            }
        }

        const __nv_bfloat16* kS  = (const __nv_bfloat16*)(sm + ASM_K0 + buf * 13312);
        const __nv_bfloat16* vhS = (const __nv_bfloat16*)(sm + ASM_V0 + buf * 18432);
        const __nv_bfloat16* vlS = vhS + 4608;   // 9216 bytes

        // ---- S = Qt Kt^T (plain bf16 MMA over K'=96) ----
        float s[8][4];
        #pragma unroll
        for (int nt = 0; nt < 8; nt++) {
            s[nt][0] = s[nt][1] = s[nt][2] = s[nt][3] = 0.f;
            int key = nt * 8 + g;
            #pragma unroll
            for (int ks = 0; ks < 6; ks++) {
                int cb = ks * 16 + 2 * tig;
                uint32_t b0 = *(const uint32_t*)&kS[key * 104 + cb];
                uint32_t b1 = *(const uint32_t*)&kS[key * 104 + cb + 8];
                mma16816(s[nt], aQ[ks], b0, b1);
            }
        }

        // ---- P = exp(S) ----
        #pragma unroll
        for (int nt = 0; nt < 8; nt++) {
            s[nt][0] = __expf(s[nt][0]);
            s[nt][1] = __expf(s[nt][1]);
            s[nt][2] = __expf(s[nt][2]);
            s[nt][3] = __expf(s[nt][3]);
            rsum0 += s[nt][0] + s[nt][1];
            rsum1 += s[nt][2] + s[nt][3];
        }

        // ---- O += P V (3-term split, P built in registers) ----
        #pragma unroll
        for (int ks = 0; ks < 4; ks++) {
            const int ta = 2 * ks, tb_ = 2 * ks + 1;
            uint32_t ah[4], al[4];
            {
                float p0 = s[ta][0],  p1 = s[ta][1];
                float h0 = bf_round(p0), h1 = bf_round(p1);
                ah[0] = pack2(h1, h0); al[0] = pack2(p1 - h1, p0 - h0);
                p0 = s[ta][2]; p1 = s[ta][3];
                h0 = bf_round(p0); h1 = bf_round(p1);
                ah[1] = pack2(h1, h0); al[1] = pack2(p1 - h1, p0 - h0);
                p0 = s[tb_][0]; p1 = s[tb_][1];
                h0 = bf_round(p0); h1 = bf_round(p1);
                ah[2] = pack2(h1, h0); al[2] = pack2(p1 - h1, p0 - h0);
                p0 = s[tb_][2]; p1 = s[tb_][3];
                h0 = bf_round(p0); h1 = bf_round(p1);
                ah[3] = pack2(h1, h0); al[3] = pack2(p1 - h1, p0 - h0);
            }
            #pragma unroll
            for (int nt = 0; nt < 8; nt++) {
                int d  = nt * 8 + g;
                int kb = ks * 16 + 2 * tig;
                uint32_t bh0 = *(const uint32_t*)&vhS[d * 72 + kb];
                uint32_t bh1 = *(const uint32_t*)&vhS[d * 72 + kb + 8];
                uint32_t bl0 = *(const uint32_t*)&vlS[d * 72 + kb];
                uint32_t bl1 = *(const uint32_t*)&vlS[d * 72 + kb + 8];
                mma16816(o[nt], ah, bh0, bh1);
                mma16816(o[nt], ah, bl0, bl1);
                mma16816(o[nt], al, bh0, bh1);
            }
        }
        __syncthreads();
        buf ^= 1;
    }

    rsum0 += __shfl_xor_sync(0xffffffffu, rsum0, 1);
    rsum0 += __shfl_xor_sync(0xffffffffu, rsum0, 2);
    rsum1 += __shfl_xor_sync(0xffffffffu, rsum1, 1);
    rsum1 += __shfl_xor_sync(0xffffffffu, rsum1, 2);
    const float inv0 = 1.f / rsum0, inv1 = 1.f / rsum1;

    __syncthreads();
    #pragma unroll
    for (int nt = 0; nt < 8; nt++) {
        int d = nt * 8 + 2 * tig;
        int q = wid * 16 + g;
        sO[d * 132 + q]           = o[nt][0] * inv0;
        sO[(d + 1) * 132 + q]     = o[nt][1] * inv0;
        sO[d * 132 + q + 8]       = o[nt][2] * inv1;
        sO[(d + 1) * 132 + q + 8] = o[nt][3] * inv1;
    }
    __syncthreads();

    const int b = bh >> 3, h = bh & 7;
    float* dst = g_att + ((size_t)b * C + h * 64) * NPIX;
    for (int idx = tid; idx < 64 * 128; idx += 256) {
        int d = idx >> 7, q = idx & 127;
        int n = q0 + q;
        if (n < NPIX) dst[(size_t)d * NPIX + n] = sO[d * 132 + q];
    }
}

// ======================= PE branch (unchanged) ==============================
__global__ __launch_bounds__(256) void pe_kernel(
    const float* __restrict__ pw,
    const float* __restrict__ gamma, const float* __restrict__ beta,
    const float* __restrict__ mean,  const float* __restrict__ var)
{
    __shared__ float img[NPIX];
    const int bc = blockIdx.x;
    const int b = bc >> 9;
    const int c = bc & 511;
    const int h = c >> 6, d = c & 63;
    const float* v = g_qkv + ((size_t)(b * NH + h) * (2 * KD + HD) + 2 * KD + d) * NPIX;
    const int tid = threadIdx.x;

    for (int l = tid; l < NPIX; l += 256) img[l] = v[l];

    float w[9];
    #pragma unroll
    for (int k = 0; k < 9; k++) w[k] = pw[c * 9 + k];
    float inv = gamma[c] * rsqrtf(var[c] + EPSV);
    float add = beta[c] - mean[c] * inv;
    __syncthreads();

    for (int l = tid; l < NPIX; l += 256) {
        int py = l / IW, px = l % IW;
        float s = 0.f;
        #pragma unroll
        for (int ky = 0; ky < 3; ky++) {
            int yy = py + ky - 1;
            if (yy < 0 || yy >= IH) continue;
            #pragma unroll
            for (int kx = 0; kx < 3; kx++) {
                int xx = px + kx - 1;
                if (xx < 0 || xx >= IW) continue;
                s += w[ky * 3 + kx] * img[yy * IW + xx];
            }
        }
        size_t idx = (size_t)bc * NPIX + l;
        g_y[idx] = s * inv + add + g_att[idx];
    }
}

// ============================================================================
extern "C" void kernel_launch(void* const* d_in, const int* in_sizes, int n_in,
                              void* d_out, int out_size)
{
    const float* x      = (const float*)d_in[0];
    const float* qkv_w  = (const float*)d_in[1];
    const float* qkv_g  = (const float*)d_in[2];
    const float* qkv_b  = (const float*)d_in[3];
    const float* qkv_m  = (const float*)d_in[4];
    const float* qkv_v  = (const float*)d_in[5];
    const float* pe_w   = (const float*)d_in[6];
    const float* pe_g   = (const float*)d_in[7];
    const float* pe_b   = (const float*)d_in[8];
    const float* pe_m   = (const float*)d_in[9];
    const float* pe_v   = (const float*)d_in[10];
    const float* proj_w = (const float*)d_in[11];
    const float* proj_g = (const float*)d_in[12];
    const float* proj_b = (const float*)d_in[13];
    const float* proj_m = (const float*)d_in[14];
    const float* proj_v = (const float*)d_in[15];
    float* out = (float*)d_out;

    float *qkv_buf, *y_buf;
    __nv_bfloat16 *wcq, *wcp, *xcb;
    cudaGetSymbolAddress((void**)&qkv_buf, g_qkv);
    cudaGetSymbolAddress((void**)&y_buf, g_y);
    cudaGetSymbolAddress((void**)&wcq, g_wcq);
    cudaGetSymbolAddress((void**)&wcp, g_wcp);
    cudaGetSymbolAddress((void**)&xcb, g_xc);

    cudaFuncSetAttribute(gemm3_bn, cudaFuncAttributeMaxDynamicSharedMemorySize, GSMEM);
    cudaFuncSetAttribute(attn2_kernel, cudaFuncAttributeMaxDynamicSharedMemorySize, ASMEM);

    // 0) operand prep (triple-bf16)
    prep_w<<<(HQKV * 512 + 255) / 256, 256>>>(qkv_w, wcq, HQKV * 512);
    prep_w<<<(C * 512 + 255) / 256, 256>>>(proj_w, wcp, C * 512);
    prep_xt<<<dim3(16, 25, B), 256>>>(x, xcb);

    // 1) qkv = BN(conv1x1(x, qkv_w))
    gemm3_bn<<<dim3(13, HQKV / 128, B), 256, GSMEM>>>(
        wcq, xcb, qkv_g, qkv_b, qkv_m, qkv_v, qkv_buf, HQKV);

    // 2a) attention operand prep
    prep_qk<<<dim3(25, 64), 256>>>();
    prep_v<<<6400, 256>>>();

    // 2b) pipelined HMMA flash attention -> g_att
    attn2_kernel<<<dim3(13, 64), 256, ASMEM>>>();

    // 3) g_y = BN(dwconv3x3(v)) + g_att
    pe_kernel<<<B * C, 256>>>(pe_w, pe_g, pe_b, pe_m, pe_v);

    // 3b) y -> triple bf16 (reuse g_xc)
    prep_xt<<<dim3(16, 25, B), 256>>>(y_buf, xcb);

    // 4) out = BN(conv1x1(y, proj_w))
    gemm3_bn<<<dim3(13, C / 128, B), 256, GSMEM>>>(
        wcp, xcb, proj_g, proj_b, proj_m, proj_v, out, C);
}